// round 3
// baseline (speedup 1.0000x reference)
#include <cuda_runtime.h>

// ---------------------------------------------------------------------------
// VQ-EMA layer, GB300 (sm_103a)
// Inputs : x [16,1024,256] f32, embed_w [1024,256] f32,
//          ema_cluster_size [1024] f32, ema_w [1024,256] f32
// Output : concat( quantized[16*1024*256], loss[1], embed_new[1024*256],
//                  cs[1024], ema_w_new[1024*256] )  -> 4,719,617 f32
// ---------------------------------------------------------------------------

constexpr int Bc = 16, Tc = 1024, Dc = 256, Kc = 1024;
constexpr int Nrows = Bc * Tc;            // 16384
constexpr int TM = 128;                   // rows per block
constexpr int TK = 64;                    // codebook cols per chunk
constexpr int NCHUNKS = Kc / TK;          // 16

constexpr float DECAYF = 0.99f;
constexpr float OMDF   = 0.01f;           // 1 - decay
constexpr float EPSF   = 1e-5f;
constexpr float KEPSF  = 0.01024f;        // K * EPS

// smem word layout for argmin kernel
constexpr int SX_STRIDE = 514;            // words per row-pair (2*256 + 2 pad)
constexpr int SX_WORDS  = (TM / 2) * SX_STRIDE;   // 64 * 514 = 32896
constexpr int SW_STRIDE = 257;            // words per codebook col (256 + 1 pad)
constexpr int SW_WORDS  = TK * SW_STRIDE;         // 64 * 257 = 16448
constexpr int SMEM_BYTES = (SX_WORDS + SW_WORDS) * 4;  // 197376 B

// ----- scratch (device globals; no allocations allowed) -----
__device__ float g_xsq[Nrows];
__device__ float g_wsq[Kc];
__device__ int   g_idx[Nrows];
__device__ float g_dw[Kc * Dc];
__device__ float g_counts[Kc];
__device__ float g_loss;
__device__ float g_cs[Kc];

// ---------------------------------------------------------------------------
// Kernel 0: row sum-of-squares for x and w; zero the scatter scratch.
// grid = Nrows + Kc blocks, 256 threads (one per d).
// ---------------------------------------------------------------------------
__global__ void prep_kernel(const float* __restrict__ x,
                            const float* __restrict__ w) {
  int b = blockIdx.x;
  int t = threadIdx.x;
  float v;
  if (b < Nrows) {
    v = x[(size_t)b * Dc + t];
  } else {
    int k = b - Nrows;
    v = w[(size_t)k * Dc + t];
    g_dw[(size_t)k * Dc + t] = 0.0f;
    if (t == 0) g_counts[k] = 0.0f;
    if (t == 1 && k == 0) g_loss = 0.0f;
  }
  float s = v * v;
  #pragma unroll
  for (int o = 16; o; o >>= 1) s += __shfl_down_sync(0xffffffffu, s, o);
  __shared__ float red[8];
  if ((t & 31) == 0) red[t >> 5] = s;
  __syncthreads();
  if (t == 0) {
    float tot = red[0];
    #pragma unroll
    for (int i = 1; i < 8; i++) tot += red[i];
    if (b < Nrows) g_xsq[b] = tot;
    else           g_wsq[b - Nrows] = tot;
  }
}

// ---------------------------------------------------------------------------
// Kernel 1: fused distance GEMM + row argmin.
//   score[n,k] = fp32( fp32(xsq[n] + wsq[k]) - 2 * dot(x[n], w[k]) )
// matching the reference's fp32 rounding structure; tie -> lowest k.
// Block: 128 rows x (all 1024 codes in 16 chunks of 64), 256 threads.
// Inner product uses packed fma.rn.f32x2 (2 fp32 MACs / instr).
// ---------------------------------------------------------------------------
__global__ void __launch_bounds__(256, 1)
argmin_kernel(const float* __restrict__ x, const float* __restrict__ w) {
  extern __shared__ float smem[];
  float* sx = smem;                 // x tile, pair-packed, d-major
  float* sw = smem + SX_WORDS;      // w chunk, col-major

  const int tid = threadIdx.x;
  const int tm = tid & 15;          // row-pair group
  const int tk = tid >> 4;          // col group
  const int rowBase = blockIdx.x * TM;

  // ---- load x tile: sx[pr*514 + par + 2*d] = x[rowBase + 2*pr + par][d]
  {
    int r    = tid >> 1;            // 0..127
    int half = tid & 1;             // which 128-d half
    int pr   = r >> 1, par = r & 1;
    const float4* src =
        reinterpret_cast<const float4*>(x + (size_t)(rowBase + r) * Dc) + half * 32;
    float* dst = sx + pr * SX_STRIDE + par;
    #pragma unroll
    for (int q = 0; q < 32; q++) {
      float4 v = src[q];
      int d = half * 128 + q * 4;
      dst[2 * d + 0] = v.x;
      dst[2 * d + 2] = v.y;
      dst[2 * d + 4] = v.z;
      dst[2 * d + 6] = v.w;
    }
  }

  float xsqv[8];
  float best[8];
  int   bidx[8];
  #pragma unroll
  for (int i = 0; i < 4; i++) {
    int pr = tm + 16 * i;
    xsqv[2 * i + 0] = g_xsq[rowBase + 2 * pr + 0];
    xsqv[2 * i + 1] = g_xsq[rowBase + 2 * pr + 1];
    best[2 * i] = best[2 * i + 1] = 3.4e38f;
    bidx[2 * i] = bidx[2 * i + 1] = 0;
  }

  for (int ck = 0; ck < NCHUNKS; ck++) {
    __syncthreads();   // previous chunk compute done (and x-tile stores on ck=0)
    // ---- load w chunk col-major: sw[col*257 + d] = w[ck*64 + col][d]
    {
      int col = tid >> 2, dseg = tid & 3;
      const float4* src =
          reinterpret_cast<const float4*>(w + (size_t)(ck * TK + col) * Dc) + dseg * 16;
      float* dst = sw + col * SW_STRIDE + dseg * 64;
      #pragma unroll
      for (int q = 0; q < 16; q++) {
        float4 v = src[q];
        dst[4 * q + 0] = v.x;
        dst[4 * q + 1] = v.y;
        dst[4 * q + 2] = v.z;
        dst[4 * q + 3] = v.w;
      }
    }
    __syncthreads();

    unsigned long long acc[4][4];
    #pragma unroll
    for (int i = 0; i < 4; i++)
      #pragma unroll
      for (int j = 0; j < 4; j++) acc[i][j] = 0ull;  // packed (0.f, 0.f)

    const float* ax0 = sx + (tm + 0)  * SX_STRIDE;
    const float* ax1 = sx + (tm + 16) * SX_STRIDE;
    const float* ax2 = sx + (tm + 32) * SX_STRIDE;
    const float* ax3 = sx + (tm + 48) * SX_STRIDE;
    const float* bw0 = sw + (tk + 0)  * SW_STRIDE;
    const float* bw1 = sw + (tk + 16) * SW_STRIDE;
    const float* bw2 = sw + (tk + 32) * SW_STRIDE;
    const float* bw3 = sw + (tk + 48) * SW_STRIDE;

    #pragma unroll 4
    for (int d = 0; d < Dc; d++) {
      unsigned long long a[4];
      a[0] = *reinterpret_cast<const unsigned long long*>(ax0 + 2 * d);
      a[1] = *reinterpret_cast<const unsigned long long*>(ax1 + 2 * d);
      a[2] = *reinterpret_cast<const unsigned long long*>(ax2 + 2 * d);
      a[3] = *reinterpret_cast<const unsigned long long*>(ax3 + 2 * d);
      float bs[4];
      bs[0] = bw0[d]; bs[1] = bw1[d]; bs[2] = bw2[d]; bs[3] = bw3[d];
      unsigned long long bp[4];
      #pragma unroll
      for (int j = 0; j < 4; j++)
        asm("mov.b64 %0, {%1, %1};" : "=l"(bp[j]) : "f"(bs[j]));
      #pragma unroll
      for (int i = 0; i < 4; i++) {
        #pragma unroll
        for (int j = 0; j < 4; j++) {
          asm("fma.rn.f32x2 %0, %1, %2, %0;"
              : "+l"(acc[i][j]) : "l"(a[i]), "l"(bp[j]));
        }
      }
    }

    // ---- scores + running argmin for this chunk
    #pragma unroll
    for (int j = 0; j < 4; j++) {
      int c = ck * TK + tk + 16 * j;
      float wsqc = g_wsq[c];
      #pragma unroll
      for (int i = 0; i < 4; i++) {
        float2 dv = *reinterpret_cast<float2*>(&acc[i][j]);
        float r1a = __fadd_rn(xsqv[2 * i + 0], wsqc);
        float s0  = __fadd_rn(r1a, -2.0f * dv.x);
        float r1b = __fadd_rn(xsqv[2 * i + 1], wsqc);
        float s1  = __fadd_rn(r1b, -2.0f * dv.y);
        if (s0 < best[2 * i + 0]) { best[2 * i + 0] = s0; bidx[2 * i + 0] = c; }
        if (s1 < best[2 * i + 1]) { best[2 * i + 1] = s1; bidx[2 * i + 1] = c; }
      }
    }
  }

  // ---- cross-thread (over tk) argmin reduction; reuse sw region
  __syncthreads();
  float* sMin = sw;                         // [16][128]
  int*   sIdx = reinterpret_cast<int*>(sw + 16 * 128);
  #pragma unroll
  for (int i = 0; i < 4; i++) {
    #pragma unroll
    for (int p = 0; p < 2; p++) {
      int r = 2 * (tm + 16 * i) + p;
      sMin[tk * 128 + r] = best[2 * i + p];
      sIdx[tk * 128 + r] = bidx[2 * i + p];
    }
  }
  __syncthreads();
  if (tid < 128) {
    float bv = sMin[tid];
    int   bi = sIdx[tid];
    #pragma unroll
    for (int t2 = 1; t2 < 16; t2++) {
      float v = sMin[t2 * 128 + tid];
      int   ii = sIdx[t2 * 128 + tid];
      if (v < bv || (v == bv && ii < bi)) { bv = v; bi = ii; }
    }
    g_idx[rowBase + tid] = bi;
  }
}

// ---------------------------------------------------------------------------
// Kernel 2: gather quantized rows, commitment-loss partial, counts & dw scatter.
// grid = Nrows blocks, 256 threads (one per d).
// ---------------------------------------------------------------------------
__global__ void gather_kernel(const float* __restrict__ x,
                              const float* __restrict__ w,
                              float* __restrict__ outQ) {
  int n = blockIdx.x;
  int d = threadIdx.x;
  int k = g_idx[n];
  float xv = x[(size_t)n * Dc + d];
  float qv = w[(size_t)k * Dc + d];
  outQ[(size_t)n * Dc + d] = qv;

  float diff = xv - qv;
  float s = diff * diff;
  #pragma unroll
  for (int o = 16; o; o >>= 1) s += __shfl_down_sync(0xffffffffu, s, o);
  __shared__ float red[8];
  if ((d & 31) == 0) red[d >> 5] = s;
  __syncthreads();
  if (d == 0) {
    float tot = red[0];
    #pragma unroll
    for (int i = 1; i < 8; i++) tot += red[i];
    atomicAdd(&g_loss, tot);
    atomicAdd(&g_counts[k], 1.0f);
  }
  atomicAdd(&g_dw[(size_t)k * Dc + d], xv);
}

// ---------------------------------------------------------------------------
// Kernel 3: cluster-size EMA + Laplace smoothing + loss write. 1 block, 1024 thr.
// ---------------------------------------------------------------------------
__global__ void cs_kernel(const float* __restrict__ ema_cs,
                          float* __restrict__ outCS,
                          float* __restrict__ outLoss) {
  int k = threadIdx.x;
  float c = ema_cs[k] * DECAYF + OMDF * g_counts[k];

  float s = c;
  #pragma unroll
  for (int o = 16; o; o >>= 1) s += __shfl_down_sync(0xffffffffu, s, o);
  __shared__ float red[32];
  if ((k & 31) == 0) red[k >> 5] = s;
  __syncthreads();
  if (k < 32) {
    float t = red[k];
    #pragma unroll
    for (int o = 16; o; o >>= 1) t += __shfl_down_sync(0xffffffffu, t, o);
    if (k == 0) red[0] = t;
  }
  __syncthreads();
  float n = red[0];

  float csf = (c + EPSF) / (n + KEPSF) * n;
  outCS[k] = csf;
  g_cs[k]  = csf;
  if (k == 0) outLoss[0] = 0.25f * g_loss / (float)((size_t)Nrows * Dc);
}

// ---------------------------------------------------------------------------
// Kernel 4: ema_w EMA + normalized embedding. K*D elements.
// ---------------------------------------------------------------------------
__global__ void ema_kernel(const float* __restrict__ ema_w,
                           float* __restrict__ outEmbed,
                           float* __restrict__ outEmaW) {
  int i = blockIdx.x * blockDim.x + threadIdx.x;   // < K*D
  float ew = ema_w[i] * DECAYF + OMDF * g_dw[i];
  outEmaW[i]  = ew;
  outEmbed[i] = ew / g_cs[i >> 8];                 // D = 256
}

// ---------------------------------------------------------------------------
extern "C" void kernel_launch(void* const* d_in, const int* in_sizes, int n_in,
                              void* d_out, int out_size) {
  const float* x      = (const float*)d_in[0];
  const float* w      = (const float*)d_in[1];
  const float* ema_cs = (const float*)d_in[2];
  const float* ema_w  = (const float*)d_in[3];

  float* out      = (float*)d_out;
  float* outQ     = out;                                   // 4,194,304
  float* outLoss  = out + (size_t)Nrows * Dc;              // 1
  float* outEmbed = outLoss + 1;                           // 262,144
  float* outCS    = outEmbed + (size_t)Kc * Dc;            // 1,024
  float* outEmaW  = outCS + Kc;                            // 262,144

  cudaFuncSetAttribute(argmin_kernel,
                       cudaFuncAttributeMaxDynamicSharedMemorySize, SMEM_BYTES);

  prep_kernel<<<Nrows + Kc, 256>>>(x, w);
  argmin_kernel<<<Nrows / TM, 256, SMEM_BYTES>>>(x, w);
  gather_kernel<<<Nrows, 256>>>(x, w, outQ);
  cs_kernel<<<1, Kc>>>(ema_cs, outCS, outLoss);
  ema_kernel<<<(Kc * Dc) / 256, 256>>>(ema_w, outEmbed, outEmaW);
}